// round 12
// baseline (speedup 1.0000x reference)
#include <cuda_runtime.h>

// PWLU channelwise activation, scalar bounds ±2.3, n_points=7 (n_regions=6).
// x: [B=64, C=256, H=56, W=56] fp32; points: [C,7]; left_diffs/right_diffs: [C].
// out = fp[c][r] + (xn - r) * df[c][r],  xn=(x-sim_left)/region_len, r=clip int.
//
// R11: software-pipelined multi-slice CTAs. 2048 CTAs x 256 threads; CTA k
// handles slices k, k+2048, ..., k+7*2048 (stride is a multiple of C=256 so
// the channel — and the 8-entry smem table — is constant per CTA). Each
// iteration prefetches the NEXT slice's 4 float4 loads before computing and
// storing the current slice, so DRAM reads stay in flight during the
// compute/store drain (R1/R4's ~25% idle tail). Stores stay evict-first (.cs).

#define BOUND_F 2.3f
#define N_POINTS 7
#define N_REGIONS 6
#define C_DIM 256
#define HW 3136            // 56*56 floats per slice
#define HW4 784            // float4 per slice
#define THREADS 256
#define N_SLICES 16384     // B*C
#define GRID 2048
#define ITERS 8            // N_SLICES / GRID

__global__ __launch_bounds__(THREADS)
void pwlu_kernel(const float* __restrict__ x,
                 const float* __restrict__ points,
                 const float* __restrict__ left_diffs,
                 const float* __restrict__ right_diffs,
                 float* __restrict__ out) {
    const int k   = blockIdx.x;             // base slice; c = k & 255 fixed
    const int c   = k & (C_DIM - 1);
    const int tid = threadIdx.x;

    // Per-channel (false_point, diff) table in shared memory (built once).
    __shared__ float2 tab[8];               // tab[r] = {fp[r], df[r]}
    if (tid < 8) {
        const float* p = points + c * N_POINTS;
        float fp, df;
        if (tid == 0)            { df = left_diffs[c];  fp = p[0] - df; }
        else if (tid == N_POINTS){ df = right_diffs[c]; fp = p[N_POINTS - 1]; }
        else                     { df = p[tid] - p[tid - 1]; fp = p[tid - 1]; }
        tab[tid] = make_float2(fp, df);
    }
    __syncthreads();

    const float region_len = (2.0f * BOUND_F) / (float)N_REGIONS;
    const float inv_rl     = (float)N_REGIONS / (2.0f * BOUND_F);
    const float sim_left   = -BOUND_F - region_len;
    const float clip_hi    = (float)(N_REGIONS + 1) * 1.001f;   // 7.007

    auto pwlu1 = [&](float xv) -> float {
        float xn = (xv - sim_left) * inv_rl;
        float rf = fminf(fmaxf(xn, 0.0f), clip_hi);
        int   r  = __float2int_rz(rf);
        float d  = xn - (float)r;
        float2 t = tab[r];
        return fmaf(d, t.y, t.x);
    };
    auto pwlu4 = [&](float4 v) -> float4 {
        float4 r;
        r.x = pwlu1(v.x); r.y = pwlu1(v.y);
        r.z = pwlu1(v.z); r.w = pwlu1(v.w);
        return r;
    };

    const bool tail = (tid < HW4 - 768);    // tid < 16

    // Prologue: load slice 0.
    const float4* xin = reinterpret_cast<const float4*>(x + (size_t)k * HW);
    float4 c0 = xin[tid];
    float4 c1 = xin[tid + 256];
    float4 c2 = xin[tid + 512];
    float4 c3;
    if (tail) c3 = xin[tid + 768];

    #pragma unroll
    for (int i = 0; i < ITERS; i++) {
        const size_t cur_base = ((size_t)k + (size_t)i * GRID) * HW;

        // Prefetch next slice BEFORE any dependent compute/store of current.
        float4 n0, n1, n2, n3;
        if (i + 1 < ITERS) {
            const float4* xn4 = reinterpret_cast<const float4*>(
                x + cur_base + (size_t)GRID * HW);
            n0 = xn4[tid];
            n1 = xn4[tid + 256];
            n2 = xn4[tid + 512];
            if (tail) n3 = xn4[tid + 768];
        }

        // Compute + store current slice (next-slice loads are in flight).
        float4* o = reinterpret_cast<float4*>(out + cur_base);
        __stcs(&o[tid],       pwlu4(c0));
        __stcs(&o[tid + 256], pwlu4(c1));
        __stcs(&o[tid + 512], pwlu4(c2));
        if (tail) __stcs(&o[tid + 768], pwlu4(c3));

        c0 = n0; c1 = n1; c2 = n2;
        if (tail) c3 = n3;
    }
}

extern "C" void kernel_launch(void* const* d_in, const int* in_sizes, int n_in,
                              void* d_out, int out_size) {
    const float* x  = (const float*)d_in[0];
    const float* p  = (const float*)d_in[1];
    const float* ld = (const float*)d_in[2];
    const float* rd = (const float*)d_in[3];
    float* out = (float*)d_out;

    pwlu_kernel<<<GRID, THREADS>>>(x, p, ld, rd, out);
}

// round 13
// speedup vs baseline: 1.0995x; 1.0995x over previous
#include <cuda_runtime.h>

// PWLU channelwise activation, scalar bounds ±2.3, n_points=7 (n_regions=6).
// x: [B=64, C=256, H=56, W=56] fp32; points: [C,7]; left_diffs/right_diffs: [C].
// out = fp[c][r] + (xn - r) * df[c][r],  xn=(x-sim_left)/region_len, r=clip int.
//
// R12: exact R4 (one CTA per (b,c) slice, float4, default loads, __stcs
// stores) with ONE reorder: the x LDG.128s are issued BEFORE the smem table
// build + __syncthreads. In R4 the barrier blocked x-load issue behind the
// points load (~250+ cyc entry bubble per CTA with zero DRAM read traffic).
// Now the barrier overlaps with x loads already in flight.

#define BOUND_F 2.3f
#define N_POINTS 7
#define N_REGIONS 6
#define C_DIM 256
#define HW 3136            // 56*56
#define HW4 784            // HW/4
#define THREADS 256

__global__ __launch_bounds__(THREADS)
void pwlu_kernel(const float* __restrict__ x,
                 const float* __restrict__ points,
                 const float* __restrict__ left_diffs,
                 const float* __restrict__ right_diffs,
                 float* __restrict__ out) {
    const int bc = blockIdx.x;          // b*C + c
    const int c  = bc & (C_DIM - 1);
    const int tid = threadIdx.x;

    const float4* __restrict__ xin = reinterpret_cast<const float4*>(x + (size_t)bc * HW);
    float4* __restrict__ o         = reinterpret_cast<float4*>(out + (size_t)bc * HW);

    // 1) Front-batch ALL x loads first — these carry the DRAM traffic and
    //    must be in flight before anything else stalls the warp.
    float4 v0 = xin[tid];
    float4 v1 = xin[tid + 256];
    float4 v2 = xin[tid + 512];
    float4 v3;
    const bool has3 = (tid < HW4 - 768);    // tid < 16
    if (has3) v3 = xin[tid + 768];

    // 2) Per-channel (false_point, diff) table build (points is L1/L2-hot
    //    after the first wave) + barrier — overlaps with x loads in flight.
    __shared__ float2 tab[8];           // tab[r] = {fp[r], df[r]}
    if (tid < 8) {
        const float* p = points + c * N_POINTS;
        float fp, df;
        if (tid == 0)            { df = left_diffs[c];  fp = p[0] - df; }
        else if (tid == N_POINTS){ df = right_diffs[c]; fp = p[N_POINTS - 1]; }
        else                     { df = p[tid] - p[tid - 1]; fp = p[tid - 1]; }
        tab[tid] = make_float2(fp, df);
    }
    __syncthreads();

    const float region_len = (2.0f * BOUND_F) / (float)N_REGIONS;
    const float inv_rl     = (float)N_REGIONS / (2.0f * BOUND_F);
    const float sim_left   = -BOUND_F - region_len;
    const float clip_hi    = (float)(N_REGIONS + 1) * 1.001f;   // 7.007

    auto pwlu1 = [&](float xv) -> float {
        float xn = (xv - sim_left) * inv_rl;
        float rf = fminf(fmaxf(xn, 0.0f), clip_hi);
        int   r  = __float2int_rz(rf);
        float d  = xn - (float)r;
        float2 t = tab[r];
        return fmaf(d, t.y, t.x);
    };
    auto pwlu4 = [&](float4 v) -> float4 {
        float4 r;
        r.x = pwlu1(v.x); r.y = pwlu1(v.y);
        r.z = pwlu1(v.z); r.w = pwlu1(v.w);
        return r;
    };

    // 3) Compute + streaming stores.
    __stcs(&o[tid],       pwlu4(v0));
    __stcs(&o[tid + 256], pwlu4(v1));
    __stcs(&o[tid + 512], pwlu4(v2));
    if (has3) __stcs(&o[tid + 768], pwlu4(v3));
}

extern "C" void kernel_launch(void* const* d_in, const int* in_sizes, int n_in,
                              void* d_out, int out_size) {
    const float* x  = (const float*)d_in[0];
    const float* p  = (const float*)d_in[1];
    const float* ld = (const float*)d_in[2];
    const float* rd = (const float*)d_in[3];
    float* out = (float*)d_out;

    const int B = 64;
    const int n_blocks = B * C_DIM;     // 16384
    pwlu_kernel<<<n_blocks, THREADS>>>(x, p, ld, rd, out);
}

// round 14
// speedup vs baseline: 1.1062x; 1.0060x over previous
#include <cuda_runtime.h>
#include <cstdint>

// PWLU channelwise activation, scalar bounds ±2.3, n_points=7 (n_regions=6).
// x: [B=64, C=256, H=56, W=56] fp32; points: [C,7]; left_diffs/right_diffs: [C].
// out = fp[c][r] + (xn - r) * df[c][r],  xn=(x-sim_left)/region_len, r=clip int.
//
// R13: R12 read side (one CTA per (b,c) slice, front-batched LDG.128 before
// table+barrier) but the WRITE path goes through SMEM + one cp.async.bulk
// (TMA bulk store) of the whole contiguous 12544-byte slice. The write
// stream reaches HBM as maximal-length bursts instead of 98 interleaved
// STG.128 wavefronts -> fewer read<->write turnarounds at the controller.

#define BOUND_F 2.3f
#define N_POINTS 7
#define N_REGIONS 6
#define C_DIM 256
#define HW 3136            // 56*56 floats per slice
#define HW4 784            // float4 per slice
#define SLICE_BYTES 12544  // HW * 4
#define THREADS 256

__global__ __launch_bounds__(THREADS)
void pwlu_kernel(const float* __restrict__ x,
                 const float* __restrict__ points,
                 const float* __restrict__ left_diffs,
                 const float* __restrict__ right_diffs,
                 float* __restrict__ out) {
    const int bc = blockIdx.x;          // b*C + c
    const int c  = bc & (C_DIM - 1);
    const int tid = threadIdx.x;

    __shared__ __align__(16) float4 sbuf[HW4];   // 12544 B staging for the slice
    __shared__ float2 tab[8];                    // tab[r] = {fp[r], df[r]}

    const float4* __restrict__ xin = reinterpret_cast<const float4*>(x + (size_t)bc * HW);

    // 1) Front-batch ALL x loads first (DRAM traffic in flight ASAP).
    float4 v0 = xin[tid];
    float4 v1 = xin[tid + 256];
    float4 v2 = xin[tid + 512];
    float4 v3;
    const bool has3 = (tid < HW4 - 768);    // tid < 16
    if (has3) v3 = xin[tid + 768];

    // 2) Table build + barrier, overlapped with x loads.
    if (tid < 8) {
        const float* p = points + c * N_POINTS;
        float fp, df;
        if (tid == 0)            { df = left_diffs[c];  fp = p[0] - df; }
        else if (tid == N_POINTS){ df = right_diffs[c]; fp = p[N_POINTS - 1]; }
        else                     { df = p[tid] - p[tid - 1]; fp = p[tid - 1]; }
        tab[tid] = make_float2(fp, df);
    }
    __syncthreads();

    const float region_len = (2.0f * BOUND_F) / (float)N_REGIONS;
    const float inv_rl     = (float)N_REGIONS / (2.0f * BOUND_F);
    const float sim_left   = -BOUND_F - region_len;
    const float clip_hi    = (float)(N_REGIONS + 1) * 1.001f;   // 7.007

    auto pwlu1 = [&](float xv) -> float {
        float xn = (xv - sim_left) * inv_rl;
        float rf = fminf(fmaxf(xn, 0.0f), clip_hi);
        int   r  = __float2int_rz(rf);
        float d  = xn - (float)r;
        float2 t = tab[r];
        return fmaf(d, t.y, t.x);
    };
    auto pwlu4 = [&](float4 v) -> float4 {
        float4 r;
        r.x = pwlu1(v.x); r.y = pwlu1(v.y);
        r.z = pwlu1(v.z); r.w = pwlu1(v.w);
        return r;
    };

    // 3) Compute into SMEM staging (conflict-free: one float4 per lane).
    sbuf[tid]       = pwlu4(v0);
    sbuf[tid + 256] = pwlu4(v1);
    sbuf[tid + 512] = pwlu4(v2);
    if (has3) sbuf[tid + 768] = pwlu4(v3);
    __syncthreads();

    // 4) One bulk store of the whole contiguous slice (max-length write burst).
    if (tid == 0) {
        asm volatile("fence.proxy.async.shared::cta;" ::: "memory");
        uint32_t s_addr;
        asm("{ .reg .u64 t; cvta.to.shared.u64 t, %1; cvt.u32.u64 %0, t; }"
            : "=r"(s_addr) : "l"(sbuf));
        float* dst = out + (size_t)bc * HW;
        asm volatile(
            "cp.async.bulk.global.shared::cta.bulk_group [%0], [%1], %2;\n\t"
            "cp.async.bulk.commit_group;\n\t"
            :: "l"(dst), "r"(s_addr), "n"(SLICE_BYTES) : "memory");
        // Keep the CTA (and its smem) alive until the bulk store completes.
        asm volatile("cp.async.bulk.wait_group 0;" ::: "memory");
    }
}

extern "C" void kernel_launch(void* const* d_in, const int* in_sizes, int n_in,
                              void* d_out, int out_size) {
    const float* x  = (const float*)d_in[0];
    const float* p  = (const float*)d_in[1];
    const float* ld = (const float*)d_in[2];
    const float* rd = (const float*)d_in[3];
    float* out = (float*)d_out;

    const int B = 64;
    const int n_blocks = B * C_DIM;     // 16384
    pwlu_kernel<<<n_blocks, THREADS>>>(x, p, ld, rd, out);
}